// round 8
// baseline (speedup 1.0000x reference)
#include <cuda_runtime.h>

#define BATCH   2
#define CF      64
#define NXD     468
#define NYD     468
#define GRID    (NXD * NYD)      // 219024
#define NP_PER  60000
#define HRD     48
#define WRD     512
#define RSP     (HRD * WRD)      // 24576
#define TCELL   64               // cells per gather tile (last tile has 16)
#define NTILES  ((GRID + TCELL - 1) / TCELL)   // 3423

// Winner-index maps: [0 .. B*G) spatial, [B*G .. 2*B*G) bev. -1 = empty.
__device__ __align__(16) int g_win[2 * BATCH * GRID];
// Channel-last transposed range_out: [B][RSP][64]
__device__ __align__(16) float g_rot[BATCH * RSP * CF];

#define SCAT_BLOCKS 625          // ceil(160000/256)
#define TRANS_BLOCKS (RSP / 32 * (CF / 32) * BATCH)   // 3072

// Fused prologue: blocks [0,625) scatter winners; blocks [625,3697) transpose
// range_out. Last-write-wins == highest point index (serial XLA scatter order).
// XLA's arcp rewrite makes v/0.16f == v*6.25f exactly (verified rel_err==0.0).
__global__ void __launch_bounds__(256) k_prologue(
        const int* __restrict__ vc, const float* __restrict__ lp,
        const float* __restrict__ ro, int n_pillar, int n_laser) {
    if (blockIdx.x < SCAT_BLOCKS) {
        int i = blockIdx.x * 256 + threadIdx.x;
        if (i < n_pillar) {
            int b   = vc[i * 4 + 0];
            int lin = vc[i * 4 + 1] + vc[i * 4 + 2] * NXD + vc[i * 4 + 3];
            if (b < 0 || b >= BATCH || lin < 0 || lin >= GRID) return;
            atomicMax(&g_win[b * GRID + lin], i);
        } else {
            int p = i - n_pillar;
            if (p >= n_laser) return;
            float x = lp[p * 5 + 1];
            float y = lp[p * 5 + 2];
            bool valid = (x > 0.0f) && (x < 69.12f) && (y > -39.68f) && (y < 39.68f)
                      && (x >= 0.0f) && (x < 468.0f) && (y >= 0.0f) && (y < 468.0f);
            if (!valid) return;
            int xi = (int)__fmul_rn(-y, 6.25f) + 248;   // XOFF
            int yi = (int)__fmul_rn(-x, 6.25f) + 432;   // YOFF
            xi = min(max(xi, 0), 495);
            yi = min(max(yi, 0), 431);
            if (xi >= NXD) return;                      // mode='drop'
            int b = p / NP_PER;
            atomicMax(&g_win[BATCH * GRID + b * GRID + yi * NXD + xi], p);
        }
    } else {
        // Transpose range_out (B,64,RSP) -> g_rot (B,RSP,64), 32x32 tiles.
        __shared__ float tile[32][33];
        int j  = blockIdx.x - SCAT_BLOCKS;
        int s0 = (j % (RSP / 32)) * 32;
        int c0 = ((j / (RSP / 32)) % (CF / 32)) * 32;
        int b  = j / (RSP / 32 * (CF / 32));
        int tx = threadIdx.x & 31, ty = threadIdx.x >> 5;   // (32, 8)
        #pragma unroll
        for (int k = 0; k < 4; k++) {
            int c = c0 + ty + k * 8;
            tile[ty + k * 8][tx] = ro[((size_t)(b * CF + c)) * RSP + s0 + tx];
        }
        __syncthreads();
        #pragma unroll
        for (int k = 0; k < 4; k++) {
            int s = s0 + ty + k * 8;
            g_rot[((size_t)(b * RSP + s)) * CF + c0 + tx] = tile[tx][ty + k * 8];
        }
    }
}

// Pipelined tiled gather, lane-cooperative gathers + XOR-swizzled smem.
// Block = 64 cells x 128 channels in 4 chunks of 32 ch, double-buffered
// (one barrier per chunk). Thread t: cell = t>>2, quad js = t&3 -> 4 lanes
// read one contiguous 64B span per winner row => 8 cache lines per warp-LDG
// (was 32). smem col swizzle col4' = (cell>>2) ^ (row&15) keeps both the
// scalar STS scatter and the LDS.128 reads bank-conflict-free.
// __stcs output stores keep the read working set L2-resident.
__global__ void __launch_bounds__(256) k_gather(
        const float* __restrict__ pf,
        const int*   __restrict__ lx,
        const int*   __restrict__ ly,
        const float* __restrict__ lp,
        float*       __restrict__ out) {
    __shared__ float buf[2][32][TCELL];    // 16 KB ping-pong chunk buffers
    __shared__ float s_zc[TCELL];
    __shared__ int   s_off[TCELL];
    __shared__ int   s_wiS[TCELL];

    int tile = blockIdx.x;
    int b    = blockIdx.y;
    int t    = threadIdx.x;
    int cell0  = tile * TCELL;
    int ncells = min(TCELL, GRID - cell0);

    if (t < TCELL) {
        int wiS = -1, wiB = -1;
        if (t < ncells) {
            wiS = g_win[b * GRID + cell0 + t];
            wiB = g_win[BATCH * GRID + b * GRID + cell0 + t];
        }
        s_wiS[t] = wiS;
        float zc = 0.0f; int off = -1;
        if (wiB >= 0) {
            float z = lp[wiB * 5 + 3];
            zc  = fminf(fmaxf(z, -2.0f), 4.0f);
            off = b * RSP + ly[wiB * 2 + 1] * WRD + lx[wiB * 2 + 1];
        }
        s_zc[t] = zc; s_off[t] = off;
    }
    __syncthreads();

    int cell = t >> 2;                     // 0..63
    int js   = t & 3;                      // quad within chunk
    int wi   = s_wiS[cell];
    int off  = s_off[cell];
    float zc = s_zc[cell];

    // Swizzled column base for this thread's scalar STS (same for all rows
    // sharing row&15, and rows js*4+k / 16+js*4+k share it).
    float4 a, r;
    {   // Prefetch chunk 0.
        a = make_float4(0.f, 0.f, 0.f, 0.f);
        if (wi >= 0) a = *(const float4*)&pf[(size_t)wi * CF + js * 4];
        r = make_float4(0.f, 0.f, 0.f, 0.f);
        if (off >= 0) {
            r = *(const float4*)&g_rot[(size_t)off * CF + js * 4];
            r.x = __fmul_rn(zc, r.x); r.y = __fmul_rn(zc, r.y);
            r.z = __fmul_rn(zc, r.z); r.w = __fmul_rn(zc, r.w);
        }
    }

    size_t base = (size_t)b * 128 * GRID + (size_t)cell0;
    #pragma unroll
    for (int c = 0; c < 4; c++) {
        float (*bc)[TCELL] = buf[c & 1];
        // Commit chunk c regs to smem (conflict-free via XOR swizzle).
        float va[4] = {a.x, a.y, a.z, a.w};
        float vr[4] = {r.x, r.y, r.z, r.w};
        #pragma unroll
        for (int k = 0; k < 4; k++) {
            int rs = js * 4 + k;           // rows rs (spatial) / 16+rs (bev)
            int col = ((((cell >> 2) ^ rs) & 15) << 2) | (cell & 3);
            bc[rs][col]      = va[k];
            bc[16 + rs][col] = vr[k];      // (16+rs)&15 == rs&15
        }
        // Issue chunk c+1 gathers; latency hides under barrier + stores.
        if (c < 3) {
            int v = (c + 1) * 4 + js;
            a = make_float4(0.f, 0.f, 0.f, 0.f);
            if (wi >= 0) a = *(const float4*)&pf[(size_t)wi * CF + v * 4];
            r = make_float4(0.f, 0.f, 0.f, 0.f);
            if (off >= 0) {
                r = *(const float4*)&g_rot[(size_t)off * CF + v * 4];
                r.x = __fmul_rn(zc, r.x); r.y = __fmul_rn(zc, r.y);
                r.z = __fmul_rn(zc, r.z); r.w = __fmul_rn(zc, r.w);
            }
        }
        __syncthreads();                   // chunk c complete in bc
        // Stream chunk c: 512 vectors (32 ch x 16 cell-quads), 2 per thread.
        #pragma unroll
        for (int it = 0; it < 2; it++) {
            int s  = t + it * 256;
            int cl = s >> 4;               // ch_local 0..31
            int cv = s & 15;               // cell quad
            if (cv * 4 < ncells) {
                int colp = (cv ^ (cl & 15)) << 2;
                float4 o = *(const float4*)&bc[cl][colp];
                int ch = (cl < 16) ? (c * 16 + cl) : (48 + c * 16 + cl);
                __stcs((float4*)&out[base + (size_t)ch * GRID + cv * 4], o);
            }
        }
        // No second barrier: next iteration's STS targets buf[(c+1)&1],
        // whose readers all retired before the sync above.
    }
}

extern "C" void kernel_launch(void* const* d_in, const int* in_sizes, int n_in,
                              void* d_out, int out_size) {
    const float* pf = (const float*)d_in[0];   // pillar_features (B*P_PER, 64)
    const int*   vc = (const int*)  d_in[1];   // voxel_coords    (B*P_PER, 4)
    const float* ro = (const float*)d_in[2];   // range_out       (B, 64, 48, 512)
    const int*   lx = (const int*)  d_in[3];   // laser_x         (B*NP, 2)
    const int*   ly = (const int*)  d_in[4];   // laser_y         (B*NP, 2)
    const float* lp = (const float*)d_in[5];   // laser_points    (B*NP, 5)
    float* out = (float*)d_out;

    int n_pillar = in_sizes[1] / 4;
    int n_laser  = in_sizes[5] / 5;

    void* winp = nullptr;
    cudaGetSymbolAddress(&winp, g_win);
    cudaMemsetAsync(winp, 0xFF, sizeof(int) * 2 * BATCH * GRID, 0);  // all -1

    k_prologue<<<SCAT_BLOCKS + TRANS_BLOCKS, 256>>>(vc, lp, ro, n_pillar, n_laser);

    dim3 gg(NTILES, BATCH);                    // (3423, 2)
    k_gather<<<gg, 256>>>(pf, lx, ly, lp, out);
}

// round 9
// speedup vs baseline: 1.0744x; 1.0744x over previous
#include <cuda_runtime.h>

#define BATCH   2
#define CF      64
#define NXD     468
#define NYD     468
#define GRID    (NXD * NYD)      // 219024
#define NP_PER  60000
#define HRD     48
#define WRD     512
#define RSP     (HRD * WRD)      // 24576
#define TCELL   64               // cells per gather tile (last tile has 16)
#define NTILES  ((GRID + TCELL - 1) / TCELL)   // 3423

// Winner-index maps: [0 .. B*G) spatial, [B*G .. 2*B*G) bev. -1 = empty.
__device__ __align__(16) int g_win[2 * BATCH * GRID];
// Channel-last transposed range_out: [B][RSP][64]
__device__ __align__(16) float g_rot[BATCH * RSP * CF];

#define SCAT_BLOCKS 625          // ceil(160000/256)
#define TRANS_BLOCKS (RSP / 32 * (CF / 32) * BATCH)   // 3072

// Fused prologue: blocks [0,625) scatter winners; blocks [625,3697) transpose
// range_out. Last-write-wins == highest point index (serial XLA scatter order).
// XLA's arcp rewrite makes v/0.16f == v*6.25f exactly (verified rel_err==0.0).
__global__ void __launch_bounds__(256) k_prologue(
        const int* __restrict__ vc, const float* __restrict__ lp,
        const float* __restrict__ ro, int n_pillar, int n_laser) {
    if (blockIdx.x < SCAT_BLOCKS) {
        int i = blockIdx.x * 256 + threadIdx.x;
        if (i < n_pillar) {
            int b   = vc[i * 4 + 0];
            int lin = vc[i * 4 + 1] + vc[i * 4 + 2] * NXD + vc[i * 4 + 3];
            if (b < 0 || b >= BATCH || lin < 0 || lin >= GRID) return;
            atomicMax(&g_win[b * GRID + lin], i);
        } else {
            int p = i - n_pillar;
            if (p >= n_laser) return;
            float x = lp[p * 5 + 1];
            float y = lp[p * 5 + 2];
            bool valid = (x > 0.0f) && (x < 69.12f) && (y > -39.68f) && (y < 39.68f)
                      && (x >= 0.0f) && (x < 468.0f) && (y >= 0.0f) && (y < 468.0f);
            if (!valid) return;
            int xi = (int)__fmul_rn(-y, 6.25f) + 248;   // XOFF
            int yi = (int)__fmul_rn(-x, 6.25f) + 432;   // YOFF
            xi = min(max(xi, 0), 495);
            yi = min(max(yi, 0), 431);
            if (xi >= NXD) return;                      // mode='drop'
            int b = p / NP_PER;
            atomicMax(&g_win[BATCH * GRID + b * GRID + yi * NXD + xi], p);
        }
    } else {
        // Transpose range_out (B,64,RSP) -> g_rot (B,RSP,64), 32x32 tiles.
        __shared__ float tile[32][33];
        int j  = blockIdx.x - SCAT_BLOCKS;
        int s0 = (j % (RSP / 32)) * 32;
        int c0 = ((j / (RSP / 32)) % (CF / 32)) * 32;
        int b  = j / (RSP / 32 * (CF / 32));
        int tx = threadIdx.x & 31, ty = threadIdx.x >> 5;   // (32, 8)
        #pragma unroll
        for (int k = 0; k < 4; k++) {
            int c = c0 + ty + k * 8;
            tile[ty + k * 8][tx] = ro[((size_t)(b * CF + c)) * RSP + s0 + tx];
        }
        __syncthreads();
        #pragma unroll
        for (int k = 0; k < 4; k++) {
            int s = s0 + ty + k * 8;
            g_rot[((size_t)(b * RSP + s)) * CF + c0 + tx] = tile[tx][ty + k * 8];
        }
    }
}

// Tiled gather with FULL-ROW coalesced loads. Block = 64 cells x 128 ch,
// processed as 2 chunks (spatial half, bev half; 64 ch each, 16 KB buffer).
// Load mapping: cell = p*16 + (t>>4), v = t&15 -> 16 lanes read one winner
// row's full 256B => 4 cache lines per warp-LDG (vs 32 in the naive map).
// STS swizzle col = cell ^ 2v: all 32 lanes of each scalar STS hit distinct
// banks. Read phase: quad (ch=cl, cells 4cv..4cv+3) lives at 16B group
// 4*(cv ^ (cl>>3)) in row cl, half-swapped when (cl>>2)&1 (branchless fix).
// Bev-half gathers issue before the spatial store phase (pipelined).
__global__ void __launch_bounds__(256) k_gather(
        const float* __restrict__ pf,
        const int*   __restrict__ lx,
        const int*   __restrict__ ly,
        const float* __restrict__ lp,
        float*       __restrict__ out) {
    __shared__ float s_val[64][64];        // 16 KB: [ch_local][swizzled cell]
    __shared__ float s_zc[TCELL];
    __shared__ int   s_off[TCELL];
    __shared__ int   s_wiS[TCELL];

    int tile = blockIdx.x;
    int b    = blockIdx.y;
    int t    = threadIdx.x;
    int cell0  = tile * TCELL;
    int ncells = min(TCELL, GRID - cell0);

    if (t < TCELL) {
        int wiS = -1, wiB = -1;
        if (t < ncells) {
            wiS = g_win[b * GRID + cell0 + t];
            wiB = g_win[BATCH * GRID + b * GRID + cell0 + t];
        }
        s_wiS[t] = wiS;
        float zc = 0.0f; int off = -1;
        if (wiB >= 0) {
            float z = lp[wiB * 5 + 3];
            zc  = fminf(fmaxf(z, -2.0f), 4.0f);
            off = b * RSP + ly[wiB * 2 + 1] * WRD + lx[wiB * 2 + 1];
        }
        s_zc[t] = zc; s_off[t] = off;
    }
    __syncthreads();

    int crel = t >> 4;                     // 0..15: cell within pass group
    int v    = t & 15;                     // quad 0..15 = full row coverage
    size_t base = (size_t)b * 128 * GRID + (size_t)cell0;

    float4 d[4];
    // ---- Chunk A (spatial): load 4 passes, full-row coalesced ----
    #pragma unroll
    for (int p = 0; p < 4; p++) {
        int cell = p * 16 + crel;
        int wi = s_wiS[cell];
        d[p] = make_float4(0.f, 0.f, 0.f, 0.f);
        if (wi >= 0) d[p] = *(const float4*)&pf[(size_t)wi * CF + v * 4];
    }
    // STS chunk A (swizzled, conflict-free).
    #pragma unroll
    for (int p = 0; p < 4; p++) {
        int cell = p * 16 + crel;
        int col  = (cell ^ (2 * v)) & 63;
        float va[4] = {d[p].x, d[p].y, d[p].z, d[p].w};
        #pragma unroll
        for (int k = 0; k < 4; k++) s_val[v * 4 + k][col] = va[k];
    }
    // ---- Prefetch chunk B (bev) into regs; hides under A's store phase ----
    #pragma unroll
    for (int p = 0; p < 4; p++) {
        int cell = p * 16 + crel;
        int off  = s_off[cell];
        float4 r = make_float4(0.f, 0.f, 0.f, 0.f);
        if (off >= 0) {
            float zc = s_zc[cell];
            r = *(const float4*)&g_rot[(size_t)off * CF + v * 4];
            r.x = __fmul_rn(zc, r.x); r.y = __fmul_rn(zc, r.y);
            r.z = __fmul_rn(zc, r.z); r.w = __fmul_rn(zc, r.w);
        }
        d[p] = r;
    }
    __syncthreads();
    // ---- Store chunk A: LDS.128 + STG.128, coalesced 256B per 16 lanes ----
    #pragma unroll
    for (int it = 0; it < 4; it++) {
        int s  = t + it * 256;
        int cl = s >> 4;                   // channel 0..63
        int cv = s & 15;                   // cell quad
        if (cv * 4 < ncells) {
            int G = cv ^ (cl >> 3);
            float4 o = *(const float4*)&s_val[cl][G * 4];
            if ((cl >> 2) & 1) o = make_float4(o.z, o.w, o.x, o.y);
            __stcs((float4*)&out[base + (size_t)cl * GRID + cv * 4], o);
        }
    }
    __syncthreads();
    // ---- STS chunk B ----
    #pragma unroll
    for (int p = 0; p < 4; p++) {
        int cell = p * 16 + crel;
        int col  = (cell ^ (2 * v)) & 63;
        float vr[4] = {d[p].x, d[p].y, d[p].z, d[p].w};
        #pragma unroll
        for (int k = 0; k < 4; k++) s_val[v * 4 + k][col] = vr[k];
    }
    __syncthreads();
    // ---- Store chunk B (channels 64..127) ----
    #pragma unroll
    for (int it = 0; it < 4; it++) {
        int s  = t + it * 256;
        int cl = s >> 4;
        int cv = s & 15;
        if (cv * 4 < ncells) {
            int G = cv ^ (cl >> 3);
            float4 o = *(const float4*)&s_val[cl][G * 4];
            if ((cl >> 2) & 1) o = make_float4(o.z, o.w, o.x, o.y);
            __stcs((float4*)&out[base + (size_t)(CF + cl) * GRID + cv * 4], o);
        }
    }
}

extern "C" void kernel_launch(void* const* d_in, const int* in_sizes, int n_in,
                              void* d_out, int out_size) {
    const float* pf = (const float*)d_in[0];   // pillar_features (B*P_PER, 64)
    const int*   vc = (const int*)  d_in[1];   // voxel_coords    (B*P_PER, 4)
    const float* ro = (const float*)d_in[2];   // range_out       (B, 64, 48, 512)
    const int*   lx = (const int*)  d_in[3];   // laser_x         (B*NP, 2)
    const int*   ly = (const int*)  d_in[4];   // laser_y         (B*NP, 2)
    const float* lp = (const float*)d_in[5];   // laser_points    (B*NP, 5)
    float* out = (float*)d_out;

    int n_pillar = in_sizes[1] / 4;
    int n_laser  = in_sizes[5] / 5;

    void* winp = nullptr;
    cudaGetSymbolAddress(&winp, g_win);
    cudaMemsetAsync(winp, 0xFF, sizeof(int) * 2 * BATCH * GRID, 0);  // all -1

    k_prologue<<<SCAT_BLOCKS + TRANS_BLOCKS, 256>>>(vc, lp, ro, n_pillar, n_laser);

    dim3 gg(NTILES, BATCH);                    // (3423, 2)
    k_gather<<<gg, 256>>>(pf, lx, ly, lp, out);
}